// round 5
// baseline (speedup 1.0000x reference)
#include <cuda_runtime.h>
#include <cuda_bf16.h>

#define FEAT_N 2
#define FEAT_C 512
#define FEAT_H 100
#define FEAT_W 152
#define NUM_ROIS 512
#define AH 14
#define AW 14
#define SPATIAL_SCALE 0.0625f
#define CH_CHUNK 8
#define CHUNKS_PER_ROI (FEAT_C / CH_CHUNK)   // 64
#define BINS (AH * AW)                       // 196

#define S_SPAN 31      // max footprint rows/cols (roi <= 27 feat px -> span <= 30)
#define S_STRIDE 33    // pad: 33 % 32 == 1 -> no vertical bank conflicts

__global__ __launch_bounds__(BINS) void roi_align_kernel(
    const float* __restrict__ feat,
    const float* __restrict__ rois,
    float* __restrict__ out)
{
    __shared__ float sfeat[CH_CHUNK][S_SPAN * S_STRIDE];   // 32.7 KB

    const int r      = blockIdx.x >> 6;          // / CHUNKS_PER_ROI
    const int chunk  = blockIdx.x & (CHUNKS_PER_ROI - 1);
    const int c0     = chunk * CH_CHUNK;

    const int tid = threadIdx.x;                 // 0..195
    const int ph  = tid / AW;
    const int pw  = tid - ph * AW;

    const float* rp = rois + r * 5;
    const int   b       = (int)rp[0];
    const float x_start = rp[1] * SPATIAL_SCALE;
    const float y_start = rp[2] * SPATIAL_SCALE;
    const float x_end   = rp[3] * SPATIAL_SCALE;
    const float y_end   = rp[4] * SPATIAL_SCALE;

    const float roi_w = fmaxf(x_end - x_start, 0.0f);
    const float roi_h = fmaxf(y_end - y_start, 0.0f);
    const float bin_h = roi_h * (1.0f / (float)(AH - 1));
    const float bin_w = roi_w * (1.0f / (float)(AW - 1));

    // ---- footprint bounds (uniform across block) ----
    const float xs0c = fminf(fmaxf(x_start, 0.0f), (float)(FEAT_W - 1));
    const float xsEc = fminf(fmaxf(x_end,   0.0f), (float)(FEAT_W - 1));
    const float ys0c = fminf(fmaxf(y_start, 0.0f), (float)(FEAT_H - 1));
    const float ysEc = fminf(fmaxf(y_end,   0.0f), (float)(FEAT_H - 1));
    const int x_lo = (int)floorf(xs0c);
    const int y_lo = (int)floorf(ys0c);
    const int x_hi = min((int)floorf(xsEc) + 1, FEAT_W - 1);  // includes x1 corner
    const int y_hi = min((int)floorf(ysEc) + 1, FEAT_H - 1);
    const int nx = x_hi - x_lo + 1;              // <= 31
    const int ny = y_hi - y_lo + 1;              // <= 31

    const int HW = FEAT_H * FEAT_W;
    const float* f = feat + ((size_t)b * FEAT_C + c0) * HW;

    // ---- phase 1: coalesced footprint load into smem (all 8 channels) ----
    const int npc = ny * nx;
    for (int e = tid; e < npc; e += BINS) {
        const int row = e / nx;
        const int col = e - row * nx;
        const int g   = (y_lo + row) * FEAT_W + x_lo + col;
        const int s   = row * S_STRIDE + col;
        #pragma unroll
        for (int cc = 0; cc < CH_CHUNK; cc++) {
            sfeat[cc][s] = __ldg(f + cc * HW + g);
        }
    }
    __syncthreads();

    // ---- phase 2: bilinear sample per bin from smem ----
    float ys = y_start + (float)ph * bin_h;
    float xs = x_start + (float)pw * bin_w;
    ys = fminf(fmaxf(ys, 0.0f), (float)(FEAT_H - 1));
    xs = fminf(fmaxf(xs, 0.0f), (float)(FEAT_W - 1));

    const int y0 = (int)floorf(ys);
    const int x0 = (int)floorf(xs);
    const int y1 = min(y0 + 1, FEAT_H - 1);
    const int x1 = min(x0 + 1, FEAT_W - 1);
    const float wy = ys - (float)y0;
    const float wx = xs - (float)x0;

    const float w00 = (1.0f - wy) * (1.0f - wx);
    const float w01 = (1.0f - wy) * wx;
    const float w10 = wy * (1.0f - wx);
    const float w11 = wy * wx;

    const int i00 = (y0 - y_lo) * S_STRIDE + (x0 - x_lo);
    const int dx  = x1 - x0;                     // 0 or 1
    const int dy  = (y1 - y0) * S_STRIDE;        // 0 or 33
    const int i01 = i00 + dx;
    const int i10 = i00 + dy;
    const int i11 = i10 + dx;

    float* op = out + ((size_t)r * FEAT_C + c0) * BINS + tid;

    #pragma unroll
    for (int cc = 0; cc < CH_CHUNK; cc++) {
        const float* sp = sfeat[cc];
        float v = w00 * sp[i00];
        v = fmaf(w01, sp[i01], v);
        v = fmaf(w10, sp[i10], v);
        v = fmaf(w11, sp[i11], v);
        op[cc * BINS] = v;
    }
}

extern "C" void kernel_launch(void* const* d_in, const int* in_sizes, int n_in,
                              void* d_out, int out_size)
{
    const float* feat = (const float*)d_in[0];
    const float* rois = (const float*)d_in[1];
    float* out = (float*)d_out;

    dim3 grid(NUM_ROIS * CHUNKS_PER_ROI);
    dim3 block(BINS);
    roi_align_kernel<<<grid, block>>>(feat, rois, out);
}

// round 6
// speedup vs baseline: 1.7768x; 1.7768x over previous
#include <cuda_runtime.h>
#include <cuda_bf16.h>

#define FEAT_C 512
#define FEAT_H 100
#define FEAT_W 152
#define NUM_ROIS 512
#define AH 14
#define AW 14
#define SPATIAL_SCALE 0.0625f
#define CH_CHUNK 8
#define CHUNKS_PER_ROI (FEAT_C / CH_CHUNK)   // 64
#define BINS (AH * AW)                       // 196
#define HW (FEAT_H * FEAT_W)

// Separable RoI-align: warp = one ph-pair; lanes hold a coalesced feature-row
// span; y-lerp lane-wise; x-interp via dynamic __shfl_sync; 28 contiguous
// outputs per warp-store. No gathers, no smem, no syncs.
__global__ __launch_bounds__(224, 7) void roi_align_kernel(
    const float* __restrict__ feat,
    const float* __restrict__ rois,
    float* __restrict__ out)
{
    const int r     = blockIdx.x >> 6;                  // / CHUNKS_PER_ROI
    const int chunk = blockIdx.x & (CHUNKS_PER_ROI - 1);
    const int c0    = chunk * CH_CHUNK;

    const int tid  = threadIdx.x;
    const int wid  = tid >> 5;                          // 0..6  -> ph pair
    const int lane = tid & 31;

    // ---- roi params ----
    const float* rp = rois + r * 5;
    const int   b       = (int)rp[0];
    const float x_start = rp[1] * SPATIAL_SCALE;
    const float y_start = rp[2] * SPATIAL_SCALE;
    const float x_end   = rp[3] * SPATIAL_SCALE;
    const float y_end   = rp[4] * SPATIAL_SCALE;

    const float roi_w = fmaxf(x_end - x_start, 0.0f);
    const float roi_h = fmaxf(y_end - y_start, 0.0f);
    const float bin_h = roi_h * (1.0f / (float)(AH - 1));
    const float bin_w = roi_w * (1.0f / (float)(AW - 1));

    // ---- x footprint (uniform): span <= 29 floats ----
    const float xs0c = fminf(fmaxf(x_start, 0.0f), (float)(FEAT_W - 1));
    const float xsEc = fminf(fmaxf(x_end,   0.0f), (float)(FEAT_W - 1));
    const int x_lo = (int)floorf(xs0c);
    const int x_hi = min((int)floorf(xsEc) + 1, FEAT_W - 1);
    const int nx   = x_hi - x_lo + 1;                   // <= 29

    // ---- per-lane x interp params ----
    // lanes 0-13 -> pw for ph_a; lanes 16-29 -> pw for ph_b; 14,15,30,31 dummies
    const int pw = (lane < 16) ? min(lane, AW - 1) : min(lane - 16, AW - 1);
    float xs = x_start + (float)pw * bin_w;
    xs = fminf(fmaxf(xs, 0.0f), (float)(FEAT_W - 1));
    const int   x0  = (int)floorf(xs);
    const int   x1  = min(x0 + 1, FEAT_W - 1);
    const float wx  = xs - (float)x0;
    const int   sx0 = x0 - x_lo;                        // in [0, nx-1]
    const int   sx1 = x1 - x_lo;                        // in [0, nx-1]

    // ---- per-warp y params (ph pair fixed per warp) ----
    const int ph_a = wid * 2;
    float ysa = y_start + (float)ph_a * bin_h;
    float ysb = y_start + (float)(ph_a + 1) * bin_h;
    ysa = fminf(fmaxf(ysa, 0.0f), (float)(FEAT_H - 1));
    ysb = fminf(fmaxf(ysb, 0.0f), (float)(FEAT_H - 1));
    const int   ya0 = (int)floorf(ysa);
    const int   ya1 = min(ya0 + 1, FEAT_H - 1);
    const float wya = ysa - (float)ya0;
    const int   yb0 = (int)floorf(ysb);
    const int   yb1 = min(yb0 + 1, FEAT_H - 1);
    const float wyb = ysb - (float)yb0;
    const bool  reuse = (yb0 == ya1);                   // adjacent bin-rows share a feature row

    const bool ldok = (lane < nx);
    const float* base = feat + ((size_t)b * FEAT_C + c0) * HW + x_lo;
    const int oa0 = ya0 * FEAT_W, oa1 = ya1 * FEAT_W;
    const int ob0 = yb0 * FEAT_W, ob1 = yb1 * FEAT_W;

    float* op = out + ((size_t)r * FEAT_C + c0) * BINS + ph_a * AW;
    const bool stok = (lane < 14) || (lane >= 16 && lane < 30);
    const int  soff = (lane < 14) ? lane : (lane - 2);  // 28 contiguous outputs

    #pragma unroll
    for (int cc = 0; cc < CH_CHUNK; cc++) {
        const float* f = base + cc * HW;
        // coalesced row-span loads (1-2 wavefronts each)
        float ra0 = ldok ? __ldg(f + oa0 + lane) : 0.0f;
        float ra1 = ldok ? __ldg(f + oa1 + lane) : 0.0f;
        float rb1 = ldok ? __ldg(f + ob1 + lane) : 0.0f;
        float rb0;
        if (reuse) {
            rb0 = ra1;                                  // uniform branch: skip one row load
        } else {
            rb0 = ldok ? __ldg(f + ob0 + lane) : 0.0f;
        }

        // y-lerp lane-wise (each lane = one feature column of the span)
        const float la = fmaf(wya, ra1 - ra0, ra0);
        const float lb = fmaf(wyb, rb1 - rb0, rb0);

        // x-interp via dynamic shuffles
        const float a0 = __shfl_sync(0xffffffffu, la, sx0);
        const float a1 = __shfl_sync(0xffffffffu, la, sx1);
        const float b0 = __shfl_sync(0xffffffffu, lb, sx0);
        const float b1 = __shfl_sync(0xffffffffu, lb, sx1);

        const float s0 = (lane < 16) ? a0 : b0;
        const float s1 = (lane < 16) ? a1 : b1;
        const float v  = fmaf(wx, s1 - s0, s0);

        if (stok) op[cc * BINS + soff] = v;             // 28 contiguous floats -> 1 wavefront
    }
}

extern "C" void kernel_launch(void* const* d_in, const int* in_sizes, int n_in,
                              void* d_out, int out_size)
{
    const float* feat = (const float*)d_in[0];
    const float* rois = (const float*)d_in[1];
    float* out = (float*)d_out;

    dim3 grid(NUM_ROIS * CHUNKS_PER_ROI);
    dim3 block(224);
    roi_align_kernel<<<grid, block>>>(feat, rois, out);
}

// round 7
// speedup vs baseline: 1.8909x; 1.0642x over previous
#include <cuda_runtime.h>
#include <cuda_bf16.h>

#define FEAT_C 512
#define FEAT_H 100
#define FEAT_W 152
#define NUM_ROIS 512
#define AH 14
#define AW 14
#define SPATIAL_SCALE 0.0625f
#define CH_CHUNK 16
#define CHUNKS_PER_ROI (FEAT_C / CH_CHUNK)   // 32
#define BINS (AH * AW)                       // 196
#define HW (FEAT_H * FEAT_W)

// Separable RoI-align, v2:
//  - warp = one ph-pair, lanes = coalesced feature-row span, y-lerp lane-wise,
//    x-interp via dynamic shuffles (unchanged from R6).
//  - CH_CHUNK 8 -> 16: amortizes per-RoI setup 2x, halves block count.
//  - chunk-major block order: 512 consecutive blocks share one 16-channel
//    feature slice (~1.9 MB) -> L2-resident, kills DRAM re-reads.
__global__ __launch_bounds__(224, 6) void roi_align_kernel(
    const float* __restrict__ feat,
    const float* __restrict__ rois,
    float* __restrict__ out)
{
    // chunk-major: consecutive blocks = same channel slice, different roi
    const int r     = blockIdx.x & (NUM_ROIS - 1);      // % 512
    const int chunk = blockIdx.x >> 9;                  // / 512
    const int c0    = chunk * CH_CHUNK;

    const int tid  = threadIdx.x;
    const int wid  = tid >> 5;                          // 0..6 -> ph pair
    const int lane = tid & 31;

    // ---- roi params ----
    const float* rp = rois + r * 5;
    const int   b       = (int)rp[0];
    const float x_start = rp[1] * SPATIAL_SCALE;
    const float y_start = rp[2] * SPATIAL_SCALE;
    const float x_end   = rp[3] * SPATIAL_SCALE;
    const float y_end   = rp[4] * SPATIAL_SCALE;

    const float roi_w = fmaxf(x_end - x_start, 0.0f);
    const float roi_h = fmaxf(y_end - y_start, 0.0f);
    const float bin_h = roi_h * (1.0f / (float)(AH - 1));
    const float bin_w = roi_w * (1.0f / (float)(AW - 1));

    // ---- x footprint (uniform across block): span <= 29 floats ----
    const float xs0c = fminf(fmaxf(x_start, 0.0f), (float)(FEAT_W - 1));
    const float xsEc = fminf(fmaxf(x_end,   0.0f), (float)(FEAT_W - 1));
    const int x_lo = (int)floorf(xs0c);
    const int x_hi = min((int)floorf(xsEc) + 1, FEAT_W - 1);
    const int nx   = x_hi - x_lo + 1;

    // ---- per-lane x interp params ----
    const int pw = (lane < 16) ? min(lane, AW - 1) : min(lane - 16, AW - 1);
    float xs = x_start + (float)pw * bin_w;
    xs = fminf(fmaxf(xs, 0.0f), (float)(FEAT_W - 1));
    const int   x0  = (int)floorf(xs);
    const int   x1  = min(x0 + 1, FEAT_W - 1);
    const float wx  = xs - (float)x0;
    const int   sx0 = x0 - x_lo;
    const int   sx1 = x1 - x_lo;

    // ---- per-warp y params ----
    const int ph_a = wid * 2;
    float ysa = y_start + (float)ph_a * bin_h;
    float ysb = y_start + (float)(ph_a + 1) * bin_h;
    ysa = fminf(fmaxf(ysa, 0.0f), (float)(FEAT_H - 1));
    ysb = fminf(fmaxf(ysb, 0.0f), (float)(FEAT_H - 1));
    const int   ya0 = (int)floorf(ysa);
    const int   ya1 = min(ya0 + 1, FEAT_H - 1);
    const float wya = ysa - (float)ya0;
    const int   yb0 = (int)floorf(ysb);
    const int   yb1 = min(yb0 + 1, FEAT_H - 1);
    const float wyb = ysb - (float)yb0;
    const bool  reuse = (yb0 == ya1);

    const bool ldok = (lane < nx);
    const float* base = feat + ((size_t)b * FEAT_C + c0) * HW + x_lo;
    const int oa0 = ya0 * FEAT_W, oa1 = ya1 * FEAT_W;
    const int ob0 = yb0 * FEAT_W, ob1 = yb1 * FEAT_W;

    float* op = out + ((size_t)r * FEAT_C + c0) * BINS + ph_a * AW;
    const bool stok = (lane < 14) || (lane >= 16 && lane < 30);
    const int  soff = (lane < 14) ? lane : (lane - 2);

    #pragma unroll
    for (int cc = 0; cc < CH_CHUNK; cc++) {
        const float* f = base + cc * HW;
        float ra0 = ldok ? __ldg(f + oa0 + lane) : 0.0f;
        float ra1 = ldok ? __ldg(f + oa1 + lane) : 0.0f;
        float rb1 = ldok ? __ldg(f + ob1 + lane) : 0.0f;
        float rb0;
        if (reuse) {
            rb0 = ra1;
        } else {
            rb0 = ldok ? __ldg(f + ob0 + lane) : 0.0f;
        }

        const float la = fmaf(wya, ra1 - ra0, ra0);
        const float lb = fmaf(wyb, rb1 - rb0, rb0);

        const float a0 = __shfl_sync(0xffffffffu, la, sx0);
        const float a1 = __shfl_sync(0xffffffffu, la, sx1);
        const float b0 = __shfl_sync(0xffffffffu, lb, sx0);
        const float b1 = __shfl_sync(0xffffffffu, lb, sx1);

        const float s0 = (lane < 16) ? a0 : b0;
        const float s1 = (lane < 16) ? a1 : b1;
        const float v  = fmaf(wx, s1 - s0, s0);

        if (stok) op[cc * BINS + soff] = v;
    }
}

extern "C" void kernel_launch(void* const* d_in, const int* in_sizes, int n_in,
                              void* d_out, int out_size)
{
    const float* feat = (const float*)d_in[0];
    const float* rois = (const float*)d_in[1];
    float* out = (float*)d_out;

    dim3 grid(NUM_ROIS * CHUNKS_PER_ROI);   // 16384, chunk-major
    dim3 block(224);
    roi_align_kernel<<<grid, block>>>(feat, rois, out);
}